// round 1
// baseline (speedup 1.0000x reference)
#include <cuda_runtime.h>

// Problem constants (shapes are fixed by the dataset; E,N taken from in_sizes).
static constexpr float F_EPS = 1e-5f;
static constexpr float IS3   = 0.57735026918962576f;  // 1/sqrt(3)
static constexpr float PN    = 0.125f;                // 1/sqrt(2*MUL) = 1/8

// Scratch (no cudaMalloc allowed): per-node edge counts + BN statistics.
static __device__ float  g_cnt[10240];
static __device__ double g_stats[96];   // [0:32) sumS, [32:64) sumS2, [64:96) sumV2

// ---------------------------------------------------------------------------
// Shared-memory layout for the main kernel. edge_attr staging is dead after
// FC1, so it is unioned with the tensor-product coefficient arrays.
// ---------------------------------------------------------------------------
struct Coefs {
    float cA[32][32];      // PN * sh0 * x0[u]
    float cD[32][32];      // PN * IS3 * (x1[u] . sh1)
    float x0[32][32];      // raw x0[u]  (block B)
    float x1[32][32][3];   // raw x1[u][i] (block C)
};
union PrepSmem {
    float EA[32][128];     // edge_attr tile (FC1 input)
    Coefs c;
};

// One 32x4 (edges x cols) x K=128 GEMM micro-tile: acc[e][c] = b2 + Hs @ W2col
__device__ __forceinline__ void gemm_chunk(
    float (&acc)[4][4],
    const float (*Hs)[128], int e0,
    const float* __restrict__ Wp,     // = W2 + chunkCol + wc*4
    const float* __restrict__ b2p)    // = b2 + chunkCol + wc*4
{
    float4 bv = *reinterpret_cast<const float4*>(b2p);
    #pragma unroll
    for (int ii = 0; ii < 4; ++ii) {
        acc[ii][0] = bv.x; acc[ii][1] = bv.y; acc[ii][2] = bv.z; acc[ii][3] = bv.w;
    }
    #pragma unroll 2
    for (int k4 = 0; k4 < 128; k4 += 4) {
        float ha[4][4];
        #pragma unroll
        for (int ii = 0; ii < 4; ++ii)
            *reinterpret_cast<float4*>(ha[ii]) =
                *reinterpret_cast<const float4*>(&Hs[e0 + ii][k4]);
        #pragma unroll
        for (int kk = 0; kk < 4; ++kk) {
            float4 wv = *reinterpret_cast<const float4*>(Wp + (k4 + kk) * 4096);
            #pragma unroll
            for (int ii = 0; ii < 4; ++ii) {
                acc[ii][0] = fmaf(ha[ii][kk], wv.x, acc[ii][0]);
                acc[ii][1] = fmaf(ha[ii][kk], wv.y, acc[ii][1]);
                acc[ii][2] = fmaf(ha[ii][kk], wv.z, acc[ii][2]);
                acc[ii][3] = fmaf(ha[ii][kk], wv.w, acc[ii][3]);
            }
        }
    }
}

// ---------------------------------------------------------------------------
// Main fused kernel: FC1 -> FC2 (streamed) -> tensor product -> scatter-add
// One CTA = 32 edges, 256 threads. Thread (ec=tid>>5, wc=tid&31) owns a
// 4-edge x 4-col micro-tile; per 128-col chunk each thread holds one u.
// The 4 lanes {wc, wc^8, wc^16, wc^24} cover 4 different u for the same
// (e, w') output, reduced with shfl before the global atomic.
// ---------------------------------------------------------------------------
__global__ __launch_bounds__(256, 2)
void k_main(const float* __restrict__ node_attr,
            const int*   __restrict__ edge_index,
            const float* __restrict__ edge_attr,
            const float* __restrict__ edge_sh,
            const float* __restrict__ W1,
            const float* __restrict__ b1,
            const float* __restrict__ W2,
            const float* __restrict__ b2,
            float* __restrict__ outacc,
            int E)
{
    __shared__ PrepSmem sp;
    __shared__ float Hs[32][128];
    __shared__ float shBC[32][4];   // [0..2] = PN*IS3*sh1[i], [3] = PN*IS3*sh0
    __shared__ int   srcs[32];

    const int tid   = threadIdx.x;
    const int wc    = tid & 31;
    const int ec    = tid >> 5;
    const int e0    = ec * 4;
    const int ebase = blockIdx.x * 32;
    const int ug    = wc >> 3;      // which u within a 4-u group

    // ---- stage edge_attr tile ----
    #pragma unroll
    for (int it = 0; it < 4; ++it) {
        int idx = tid + it * 256;          // 1024 float4 slots
        int e = idx >> 5, q = idx & 31;
        int eg = ebase + e;
        float4 v = make_float4(0.f, 0.f, 0.f, 0.f);
        if (eg < E)
            v = *reinterpret_cast<const float4*>(edge_attr + (size_t)eg * 128 + q * 4);
        *reinterpret_cast<float4*>(&sp.EA[e][q * 4]) = v;
    }
    __syncthreads();

    // ---- FC1: Hs = relu(EA @ W1 + b1) ----
    {
        float acc[4][4];
        #pragma unroll
        for (int ii = 0; ii < 4; ++ii)
            acc[ii][0] = acc[ii][1] = acc[ii][2] = acc[ii][3] = 0.f;
        const float* W1p = W1 + wc * 4;
        #pragma unroll 2
        for (int k4 = 0; k4 < 128; k4 += 4) {
            float ha[4][4];
            #pragma unroll
            for (int ii = 0; ii < 4; ++ii)
                *reinterpret_cast<float4*>(ha[ii]) =
                    *reinterpret_cast<const float4*>(&sp.EA[e0 + ii][k4]);
            #pragma unroll
            for (int kk = 0; kk < 4; ++kk) {
                float4 wv = *reinterpret_cast<const float4*>(W1p + (k4 + kk) * 128);
                #pragma unroll
                for (int ii = 0; ii < 4; ++ii) {
                    acc[ii][0] = fmaf(ha[ii][kk], wv.x, acc[ii][0]);
                    acc[ii][1] = fmaf(ha[ii][kk], wv.y, acc[ii][1]);
                    acc[ii][2] = fmaf(ha[ii][kk], wv.z, acc[ii][2]);
                    acc[ii][3] = fmaf(ha[ii][kk], wv.w, acc[ii][3]);
                }
            }
        }
        float b1a[4];
        *reinterpret_cast<float4*>(b1a) =
            *reinterpret_cast<const float4*>(b1 + wc * 4);
        #pragma unroll
        for (int ii = 0; ii < 4; ++ii)
            #pragma unroll
            for (int cc = 0; cc < 4; ++cc)
                Hs[e0 + ii][wc * 4 + cc] = fmaxf(acc[ii][cc] + b1a[cc], 0.f);
    }
    __syncthreads();   // FC1 done: EA region may now be overwritten by coefs

    // ---- per-edge tensor-product coefficients (8 threads / edge) ----
    {
        int e = tid >> 3, j = tid & 7;
        int eg = ebase + e;
        if (eg < E) {
            float4 shv = *reinterpret_cast<const float4*>(edge_sh + (size_t)eg * 4);
            if (j == 0) {
                int src = edge_index[eg];
                srcs[e] = src;
                shBC[e][0] = PN * IS3 * shv.y;
                shBC[e][1] = PN * IS3 * shv.z;
                shBC[e][2] = PN * IS3 * shv.w;
                shBC[e][3] = PN * IS3 * shv.x;
                atomicAdd(&g_cnt[src], 1.0f);
            }
            int dst = edge_index[E + eg];
            const float* xr = node_attr + (size_t)dst * 128;
            float x0a[4];
            *reinterpret_cast<float4*>(x0a) =
                *reinterpret_cast<const float4*>(xr + j * 4);
            float x1a[12];
            #pragma unroll
            for (int t = 0; t < 6; ++t)
                *reinterpret_cast<float2*>(&x1a[t * 2]) =
                    *reinterpret_cast<const float2*>(xr + 32 + j * 12 + t * 2);
            #pragma unroll
            for (int t = 0; t < 4; ++t) {
                int u = j * 4 + t;
                sp.c.x0[e][u] = x0a[t];
                sp.c.cA[e][u] = PN * shv.x * x0a[t];
                float d = x1a[3*t] * shv.y + x1a[3*t+1] * shv.z + x1a[3*t+2] * shv.w;
                sp.c.cD[e][u] = PN * IS3 * d;
                sp.c.x1[e][u][0] = x1a[3*t];
                sp.c.x1[e][u][1] = x1a[3*t+1];
                sp.c.x1[e][u][2] = x1a[3*t+2];
            }
        } else {
            if (j == 0) {
                srcs[e] = 0;
                shBC[e][0] = shBC[e][1] = shBC[e][2] = shBC[e][3] = 0.f;
            }
            #pragma unroll
            for (int t = 0; t < 4; ++t) {
                int u = j * 4 + t;
                sp.c.x0[e][u] = 0.f; sp.c.cA[e][u] = 0.f; sp.c.cD[e][u] = 0.f;
                sp.c.x1[e][u][0] = sp.c.x1[e][u][1] = sp.c.x1[e][u][2] = 0.f;
            }
        }
    }
    __syncthreads();

    // ================= Phase A + D : scalar output out0 =================
    float out0[4][4];
    #pragma unroll
    for (int ii = 0; ii < 4; ++ii)
        out0[ii][0] = out0[ii][1] = out0[ii][2] = out0[ii][3] = 0.f;

    #pragma unroll 1
    for (int cb = 0; cb < 16; ++cb) {
        int ci = cb & 7;
        int xoff = (cb < 8) ? 0 : 3072;           // block A then block D
        int u = ci * 4 + ug;
        const float* Wp = W2 + xoff + ci * 128 + wc * 4;
        const float* bp = b2 + xoff + ci * 128 + wc * 4;
        float acc[4][4];
        gemm_chunk(acc, Hs, e0, Wp, bp);
        #pragma unroll
        for (int ii = 0; ii < 4; ++ii) {
            float coef = (cb < 8) ? sp.c.cA[e0 + ii][u] : sp.c.cD[e0 + ii][u];
            #pragma unroll
            for (int cc = 0; cc < 4; ++cc)
                out0[ii][cc] = fmaf(coef, acc[ii][cc], out0[ii][cc]);
        }
    }
    #pragma unroll
    for (int ii = 0; ii < 4; ++ii)
        #pragma unroll
        for (int cc = 0; cc < 4; ++cc) {
            float v = out0[ii][cc];
            v += __shfl_xor_sync(0xffffffffu, v, 8);
            v += __shfl_xor_sync(0xffffffffu, v, 16);
            out0[ii][cc] = v;
        }
    if (wc < 8) {
        #pragma unroll
        for (int ii = 0; ii < 4; ++ii) {
            float* op = outacc + (size_t)srcs[e0 + ii] * 128 + wc * 4;
            #pragma unroll
            for (int cc = 0; cc < 4; ++cc)
                atomicAdd(op + cc, out0[ii][cc]);
        }
    }

    // ================= Phase B : tB[w] = sum_u x0[u]*wB[u,w] =================
    float tB[4][4];
    #pragma unroll
    for (int ii = 0; ii < 4; ++ii)
        tB[ii][0] = tB[ii][1] = tB[ii][2] = tB[ii][3] = 0.f;

    #pragma unroll 1
    for (int ci = 0; ci < 8; ++ci) {
        int u = ci * 4 + ug;
        const float* Wp = W2 + 1024 + ci * 128 + wc * 4;
        const float* bp = b2 + 1024 + ci * 128 + wc * 4;
        float acc[4][4];
        gemm_chunk(acc, Hs, e0, Wp, bp);
        #pragma unroll
        for (int ii = 0; ii < 4; ++ii) {
            float coef = sp.c.x0[e0 + ii][u];
            #pragma unroll
            for (int cc = 0; cc < 4; ++cc)
                tB[ii][cc] = fmaf(coef, acc[ii][cc], tB[ii][cc]);
        }
    }

    // ============ Phase C : vC[w][i] = sum_u x1[u][i]*wC[u,w] ============
    float vC[4][4][3];
    #pragma unroll
    for (int ii = 0; ii < 4; ++ii)
        #pragma unroll
        for (int cc = 0; cc < 4; ++cc)
            vC[ii][cc][0] = vC[ii][cc][1] = vC[ii][cc][2] = 0.f;

    #pragma unroll 1
    for (int ci = 0; ci < 8; ++ci) {
        int u = ci * 4 + ug;
        const float* Wp = W2 + 2048 + ci * 128 + wc * 4;
        const float* bp = b2 + 2048 + ci * 128 + wc * 4;
        float acc[4][4];
        gemm_chunk(acc, Hs, e0, Wp, bp);
        #pragma unroll
        for (int ii = 0; ii < 4; ++ii) {
            float c0 = sp.c.x1[e0 + ii][u][0];
            float c1 = sp.c.x1[e0 + ii][u][1];
            float c2 = sp.c.x1[e0 + ii][u][2];
            #pragma unroll
            for (int cc = 0; cc < 4; ++cc) {
                vC[ii][cc][0] = fmaf(c0, acc[ii][cc], vC[ii][cc][0]);
                vC[ii][cc][1] = fmaf(c1, acc[ii][cc], vC[ii][cc][1]);
                vC[ii][cc][2] = fmaf(c2, acc[ii][cc], vC[ii][cc][2]);
            }
        }
    }

    // ---- reduce over u-lane groups, combine B+C, scatter out1 ----
    #pragma unroll
    for (int ii = 0; ii < 4; ++ii)
        #pragma unroll
        for (int cc = 0; cc < 4; ++cc) {
            float v = tB[ii][cc];
            v += __shfl_xor_sync(0xffffffffu, v, 8);
            v += __shfl_xor_sync(0xffffffffu, v, 16);
            tB[ii][cc] = v;
            #pragma unroll
            for (int i3 = 0; i3 < 3; ++i3) {
                float w = vC[ii][cc][i3];
                w += __shfl_xor_sync(0xffffffffu, w, 8);
                w += __shfl_xor_sync(0xffffffffu, w, 16);
                vC[ii][cc][i3] = w;
            }
        }
    if (wc < 8) {
        #pragma unroll
        for (int ii = 0; ii < 4; ++ii) {
            int e = e0 + ii;
            float sb0 = shBC[e][0], sb1 = shBC[e][1], sb2 = shBC[e][2];
            float sc  = shBC[e][3];
            float* op = outacc + (size_t)srcs[e] * 128 + 32 + wc * 12;
            #pragma unroll
            for (int cc = 0; cc < 4; ++cc) {
                float t = tB[ii][cc];
                atomicAdd(op + cc * 3 + 0, fmaf(sb0, t, sc * vC[ii][cc][0]));
                atomicAdd(op + cc * 3 + 1, fmaf(sb1, t, sc * vC[ii][cc][1]));
                atomicAdd(op + cc * 3 + 2, fmaf(sb2, t, sc * vC[ii][cc][2]));
            }
        }
    }
}

// ---------------------------------------------------------------------------
// Zero accumulators (out is also the segment-sum accumulator).
// ---------------------------------------------------------------------------
__global__ void k_zero(float* __restrict__ outp, int n_out, int N)
{
    int i = blockIdx.x * blockDim.x + threadIdx.x;
    int stride = gridDim.x * blockDim.x;
    for (int t = i; t < n_out; t += stride) outp[t] = 0.f;
    for (int t = i; t < N;     t += stride) g_cnt[t] = 0.f;
    for (int t = i; t < 96;    t += stride) g_stats[t] = 0.0;
}

// ---------------------------------------------------------------------------
// Mean over incoming edges + residual, and BN statistics (double accumulation).
// 256 threads = 32 rows x 8 threads; writes the pre-BN value back to out.
// ---------------------------------------------------------------------------
__global__ __launch_bounds__(256)
void k_stats(float* __restrict__ outp, const float* __restrict__ node_attr, int N)
{
    __shared__ float sS[32], sS2[32], sV2[32];
    int tid = threadIdx.x;
    if (tid < 32) { sS[tid] = 0.f; sS2[tid] = 0.f; sV2[tid] = 0.f; }
    __syncthreads();

    int r = blockIdx.x * 32 + (tid >> 3);
    int j = tid & 7;
    if (r < N) {
        float inv = 1.0f / fmaxf(g_cnt[r], 1.0f);
        size_t base = (size_t)r * 128 + j * 16;
        float v[16];
        #pragma unroll
        for (int t = 0; t < 4; ++t) {
            float4 a = *reinterpret_cast<const float4*>(outp + base + t * 4);
            float4 b = *reinterpret_cast<const float4*>(node_attr + base + t * 4);
            v[t*4+0] = fmaf(a.x, inv, b.x);
            v[t*4+1] = fmaf(a.y, inv, b.y);
            v[t*4+2] = fmaf(a.z, inv, b.z);
            v[t*4+3] = fmaf(a.w, inv, b.w);
            float4 w = make_float4(v[t*4+0], v[t*4+1], v[t*4+2], v[t*4+3]);
            *reinterpret_cast<float4*>(outp + base + t * 4) = w;
        }
        if (j < 2) {
            #pragma unroll
            for (int t = 0; t < 16; ++t) {
                int c = j * 16 + t;
                atomicAdd(&sS[c],  v[t]);
                atomicAdd(&sS2[c], v[t] * v[t]);
            }
        } else {
            #pragma unroll
            for (int t = 0; t < 16; ++t) {
                int c = j * 16 + t;
                atomicAdd(&sV2[(c - 32) / 3], v[t] * v[t]);
            }
        }
    }
    __syncthreads();
    if (tid < 32) {
        atomicAdd(&g_stats[tid],      (double)sS[tid]);
        atomicAdd(&g_stats[32 + tid], (double)sS2[tid]);
        atomicAdd(&g_stats[64 + tid], (double)sV2[tid]);
    }
}

// ---------------------------------------------------------------------------
// Finalize BN: per-channel scale/shift computed once per CTA, then applied.
// ---------------------------------------------------------------------------
__global__ void k_apply(float* __restrict__ outp,
                        const float* __restrict__ bnw,
                        const float* __restrict__ bnb,
                        int N, int total)
{
    __shared__ float pAll[128], qAll[128];
    int tid = threadIdx.x;
    if (tid < 128) {
        float p, q = 0.f;
        if (tid < 32) {
            double meanS = g_stats[tid] / N;
            double var   = g_stats[32 + tid] / N - meanS * meanS;
            p = rsqrtf((float)var + F_EPS) * bnw[tid];
            q = bnb[tid] - (float)meanS * p;
        } else {
            int u = (tid - 32) / 3;
            double mv = g_stats[64 + u] / (3.0 * N);
            p = rsqrtf((float)mv + F_EPS) * bnw[32 + u];
        }
        pAll[tid] = p; qAll[tid] = q;
    }
    __syncthreads();
    int stride = gridDim.x * blockDim.x;
    for (int i = blockIdx.x * blockDim.x + tid; i < total; i += stride) {
        int c = i & 127;
        outp[i] = fmaf(outp[i], pAll[c], qAll[c]);
    }
}

// ---------------------------------------------------------------------------
extern "C" void kernel_launch(void* const* d_in, const int* in_sizes, int n_in,
                              void* d_out, int out_size)
{
    const float* node_attr  = (const float*)d_in[0];
    const int*   edge_index = (const int*)  d_in[1];
    const float* edge_attr  = (const float*)d_in[2];
    const float* edge_sh    = (const float*)d_in[3];
    const float* W1         = (const float*)d_in[4];
    const float* b1         = (const float*)d_in[5];
    const float* W2         = (const float*)d_in[6];
    const float* b2         = (const float*)d_in[7];
    const float* bnw        = (const float*)d_in[8];
    const float* bnb        = (const float*)d_in[9];
    float* outp = (float*)d_out;

    const int N = in_sizes[0] / 128;
    const int E = in_sizes[2] / 128;

    k_zero <<<256, 256>>>(outp, out_size, N);
    k_main <<<(E + 31) / 32, 256>>>(node_attr, edge_index, edge_attr, edge_sh,
                                    W1, b1, W2, b2, outp, E);
    k_stats<<<(N + 31) / 32, 256>>>(outp, node_attr, N);
    k_apply<<<512, 256>>>(outp, bnw, bnb, N, out_size);
}